// round 7
// baseline (speedup 1.0000x reference)
#include <cuda_runtime.h>
#include <cstdint>

// LogicGatedSNN: spikes = (membrane + x · (states > 50)^T + noise) >= threshold
// x: [8192] fp32 binary, states: [8192, 8192] fp32, out: [8192] fp32
//
// DRAM-bound 256 MiB single-pass stream. x packed once into a 1KiB bitmask.
// Persistent grid-stride main kernel: each CTA loops rows with stride=grid,
// double-buffering rows in registers so the next row's 8 LDG.128 are in
// flight during the current row's reduction/epilogue. No CTA relaunch gaps.

#define IN_F   8192
#define OUT_F  8192
#define NTHR   256
#define NWARPS (NTHR / 32)
#define VEC    (IN_F / 4 / NTHR)          // 8 float4 per thread per row
#define GRID   (8 * 148)                  // 1184 persistent CTAs

// Packed x: word t holds bits for thread-slot t's 32 columns.
// bit (4*j + c) = x[4*(j*NTHR + t) + c] != 0
__device__ unsigned g_xbits[NTHR];

__global__ __launch_bounds__(NTHR) void pack_x_kernel(const float* __restrict__ x)
{
    const int tid = threadIdx.x;
    const float4* __restrict__ x4 = reinterpret_cast<const float4*>(x);
    unsigned w = 0;
    #pragma unroll
    for (int j = 0; j < VEC; ++j) {
        const float4 v = x4[j * NTHR + tid];
        unsigned nib = (v.x != 0.0f ? 1u : 0u)
                     | (v.y != 0.0f ? 2u : 0u)
                     | (v.z != 0.0f ? 4u : 0u)
                     | (v.w != 0.0f ? 8u : 0u);
        w |= nib << (4 * j);
    }
    g_xbits[tid] = w;
}

__device__ __forceinline__ void load_row(float4 (&buf)[VEC],
                                         const float* __restrict__ states,
                                         int row, int tid)
{
    const float4* __restrict__ s4 =
        reinterpret_cast<const float4*>(states + (size_t)row * IN_F);
    #pragma unroll
    for (int j = 0; j < VEC; ++j)
        buf[j] = __ldcs(&s4[j * NTHR + tid]);
}

__device__ __forceinline__ void consume_row(const float4 (&buf)[VEC],
                                            unsigned X, int row, int tid,
                                            int (*wsum)[NWARPS], int parity,
                                            const float* __restrict__ mem,
                                            const float* __restrict__ thr,
                                            const float* __restrict__ noise,
                                            float* __restrict__ out)
{
    int cnt = 0;
    #pragma unroll
    for (int j = 0; j < VEC; ++j) {
        const unsigned nib = X >> (4 * j);
        cnt += (buf[j].x > 50.0f) & (int)(nib & 1u);
        cnt += (buf[j].y > 50.0f) & (int)((nib >> 1) & 1u);
        cnt += (buf[j].z > 50.0f) & (int)((nib >> 2) & 1u);
        cnt += (buf[j].w > 50.0f) & (int)((nib >> 3) & 1u);
    }

    cnt = __reduce_add_sync(0xffffffffu, cnt);   // REDUX, one op

    if ((tid & 31) == 0) wsum[parity][tid >> 5] = cnt;
    __syncthreads();

    if (tid == 0) {
        int c = 0;
        #pragma unroll
        for (int w = 0; w < NWARPS; ++w)
            c += wsum[parity][w];
        const float p = mem[row] + (float)c + noise[row];
        out[row] = (p >= thr[row]) ? 1.0f : 0.0f;
    }
}

__global__ __launch_bounds__(NTHR, 3) void snn_persist_kernel(
    const float* __restrict__ states,   // [OUT_F, IN_F]
    const float* __restrict__ mem,      // [OUT_F]
    const float* __restrict__ thr,      // [OUT_F]
    const float* __restrict__ noise,    // [OUT_F]
    float* __restrict__ out)            // [OUT_F]
{
    __shared__ int wsum[2][NWARPS];

    const int tid = threadIdx.x;
    const unsigned X = g_xbits[tid];     // 1KiB total, L1-hot

    int row = blockIdx.x;                // GRID < OUT_F: every CTA has >= 1 row
    float4 a[VEC], b[VEC];

    load_row(a, states, row, tid);

    for (;;) {
        // Prefetch next row into b while a is reduced
        const int r1 = row + GRID;
        if (r1 < OUT_F) load_row(b, states, r1, tid);
        consume_row(a, X, row, tid, wsum, 0, mem, thr, noise, out);
        if (r1 >= OUT_F) break;
        row = r1;

        // Prefetch following row into a while b is reduced
        const int r2 = row + GRID;
        if (r2 < OUT_F) load_row(a, states, r2, tid);
        consume_row(b, X, row, tid, wsum, 1, mem, thr, noise, out);
        if (r2 >= OUT_F) break;
        row = r2;
    }
}

extern "C" void kernel_launch(void* const* d_in, const int* in_sizes, int n_in,
                              void* d_out, int out_size) {
    const float* x      = (const float*)d_in[0];  // spike_input [1, 8192]
    const float* states = (const float*)d_in[1];  // synapse_states [8192, 8192]
    const float* mem    = (const float*)d_in[2];  // membrane_potential [8192]
    const float* thr    = (const float*)d_in[3];  // adaptive_threshold [8192]
    const float* noise  = (const float*)d_in[4];  // noise [8192]
    float* out = (float*)d_out;                   // spikes [8192]

    pack_x_kernel<<<1, NTHR>>>(x);
    snn_persist_kernel<<<GRID, NTHR>>>(states, mem, thr, noise, out);
}

// round 8
// speedup vs baseline: 1.3275x; 1.3275x over previous
#include <cuda_runtime.h>
#include <cstdint>

// LogicGatedSNN: spikes = (membrane + x · (states > 50)^T + noise) >= threshold
// x: [8192] fp32 binary, states: [8192, 8192] fp32, out: [8192] fp32
//
// DRAM-bound 256 MiB single-pass stream. x packed once into a 1KiB bitmask
// (1 LDG.32 per thread in the main kernel). CTA-per-row, MLP=8 LDG.128.
// Tail minimized: row scalars (mem/thr/noise) prefetched at kernel entry so
// their latency hides under the stream wait; warp reduction via REDUX.

#define IN_F   8192
#define OUT_F  8192
#define NTHR   256
#define NWARPS (NTHR / 32)
#define VEC    (IN_F / 4 / NTHR)           // 8 float4 per thread

// Packed x: word t holds bits for thread-slot t's 32 columns.
// bit (4*j + c) = x[4*(j*NTHR + t) + c] != 0
__device__ unsigned g_xbits[NTHR];

__global__ __launch_bounds__(NTHR) void pack_x_kernel(const float* __restrict__ x)
{
    const int tid = threadIdx.x;
    const float4* __restrict__ x4 = reinterpret_cast<const float4*>(x);
    unsigned w = 0;
    #pragma unroll
    for (int j = 0; j < VEC; ++j) {
        const float4 v = x4[j * NTHR + tid];
        unsigned nib = (v.x != 0.0f ? 1u : 0u)
                     | (v.y != 0.0f ? 2u : 0u)
                     | (v.z != 0.0f ? 4u : 0u)
                     | (v.w != 0.0f ? 8u : 0u);
        w |= nib << (4 * j);
    }
    g_xbits[tid] = w;
}

__global__ __launch_bounds__(NTHR) void snn_bits_kernel(
    const float* __restrict__ states,   // [OUT_F, IN_F]
    const float* __restrict__ mem,      // [OUT_F]
    const float* __restrict__ thr,      // [OUT_F]
    const float* __restrict__ noise,    // [OUT_F]
    float* __restrict__ out)            // [OUT_F]
{
    __shared__ int wsum[NWARPS];

    const int tid = threadIdx.x;
    const int row = blockIdx.x;

    // Prefetch row scalars early (tid0 only) — latency overlaps stream wait.
    float pm = 0.0f, pn = 0.0f, pt = 0.0f;
    if (tid == 0) {
        pm = __ldg(&mem[row]);
        pn = __ldg(&noise[row]);
        pt = __ldg(&thr[row]);
    }

    const float4* __restrict__ s4 =
        reinterpret_cast<const float4*>(states + (size_t)row * IN_F);

    // states row: 8 independent streaming LDG.128 per thread
    float4 s[VEC];
    #pragma unroll
    for (int j = 0; j < VEC; ++j)
        s[j] = __ldcs(&s4[j * NTHR + tid]);

    const unsigned X = g_xbits[tid];     // 1KiB total, L1-hot

    int cnt = 0;
    #pragma unroll
    for (int j = 0; j < VEC; ++j) {
        const unsigned nib = X >> (4 * j);
        cnt += (s[j].x > 50.0f) & (int)(nib & 1u);
        cnt += (s[j].y > 50.0f) & (int)((nib >> 1) & 1u);
        cnt += (s[j].z > 50.0f) & (int)((nib >> 2) & 1u);
        cnt += (s[j].w > 50.0f) & (int)((nib >> 3) & 1u);
    }

    // One-instruction warp reduction
    cnt = __reduce_add_sync(0xffffffffu, cnt);

    if ((tid & 31) == 0) wsum[tid >> 5] = cnt;
    __syncthreads();

    if (tid == 0) {
        int c = 0;
        #pragma unroll
        for (int w = 0; w < NWARPS; ++w)
            c += wsum[w];
        const float p = pm + (float)c + pn;
        out[row] = (p >= pt) ? 1.0f : 0.0f;
    }
}

extern "C" void kernel_launch(void* const* d_in, const int* in_sizes, int n_in,
                              void* d_out, int out_size) {
    const float* x      = (const float*)d_in[0];  // spike_input [1, 8192]
    const float* states = (const float*)d_in[1];  // synapse_states [8192, 8192]
    const float* mem    = (const float*)d_in[2];  // membrane_potential [8192]
    const float* thr    = (const float*)d_in[3];  // adaptive_threshold [8192]
    const float* noise  = (const float*)d_in[4];  // noise [8192]
    float* out = (float*)d_out;                   // spikes [8192]

    pack_x_kernel<<<1, NTHR>>>(x);
    snn_bits_kernel<<<OUT_F, NTHR>>>(states, mem, thr, noise, out);
}

// round 9
// speedup vs baseline: 1.3353x; 1.0059x over previous
#include <cuda_runtime.h>
#include <cstdint>

// LogicGatedSNN: spikes = (membrane + x · (states > 50)^T + noise) >= threshold
// x: [8192] fp32 binary, states: [8192, 8192] fp32, out: [8192] fp32
//
// DRAM-bound 256 MiB single-pass stream. x packed once into a 1KiB bitmask
// (1 LDG.32 per thread in the main kernel). CTA-per-row, MLP=8 LDG.128
// (R5 structure — best measured: 82.5% DRAM).
// NEW: PDL overlap — main kernel launched with programmatic stream
// serialization; it issues its states loads first, then
// cudaGridDependencySynchronize() before touching g_xbits, hiding the pack
// kernel + launch gap (~1.9us) under the main kernel's prologue.

#define IN_F   8192
#define OUT_F  8192
#define NTHR   256
#define NWARPS (NTHR / 32)
#define VEC    (IN_F / 4 / NTHR)           // 8 float4 per thread

// Packed x: word t holds bits for thread-slot t's 32 columns.
// bit (4*j + c) = x[4*(j*NTHR + t) + c] != 0
__device__ unsigned g_xbits[NTHR];

__global__ __launch_bounds__(NTHR) void pack_x_kernel(const float* __restrict__ x)
{
    const int tid = threadIdx.x;
    const float4* __restrict__ x4 = reinterpret_cast<const float4*>(x);
    unsigned w = 0;
    #pragma unroll
    for (int j = 0; j < VEC; ++j) {
        const float4 v = x4[j * NTHR + tid];
        unsigned nib = (v.x != 0.0f ? 1u : 0u)
                     | (v.y != 0.0f ? 2u : 0u)
                     | (v.z != 0.0f ? 4u : 0u)
                     | (v.w != 0.0f ? 8u : 0u);
        w |= nib << (4 * j);
    }
    g_xbits[tid] = w;
    // Release the dependent grid as soon as the bitmask is written.
    cudaTriggerProgrammaticLaunchCompletion();
}

__global__ __launch_bounds__(NTHR) void snn_bits_kernel(
    const float* __restrict__ states,   // [OUT_F, IN_F]
    const float* __restrict__ mem,      // [OUT_F]
    const float* __restrict__ thr,      // [OUT_F]
    const float* __restrict__ noise,    // [OUT_F]
    float* __restrict__ out)            // [OUT_F]
{
    __shared__ int wsum[NWARPS];

    const int tid = threadIdx.x;
    const int row = blockIdx.x;

    const float4* __restrict__ s4 =
        reinterpret_cast<const float4*>(states + (size_t)row * IN_F);

    // states row: 8 independent streaming LDG.128 per thread.
    // These do NOT depend on the pack kernel, so issue them before the
    // PDL dependency sync — pack latency hides under the stream fill.
    float4 s[VEC];
    #pragma unroll
    for (int j = 0; j < VEC; ++j)
        s[j] = __ldcs(&s4[j * NTHR + tid]);

    // Wait for pack_x_kernel's trigger before reading g_xbits.
    cudaGridDependencySynchronize();
    const unsigned X = g_xbits[tid];     // 1KiB total, L1-hot

    int cnt = 0;
    #pragma unroll
    for (int j = 0; j < VEC; ++j) {
        const unsigned nib = X >> (4 * j);
        cnt += (s[j].x > 50.0f) & (int)(nib & 1u);
        cnt += (s[j].y > 50.0f) & (int)((nib >> 1) & 1u);
        cnt += (s[j].z > 50.0f) & (int)((nib >> 2) & 1u);
        cnt += (s[j].w > 50.0f) & (int)((nib >> 3) & 1u);
    }

    // Warp reduce (int)
    #pragma unroll
    for (int off = 16; off > 0; off >>= 1)
        cnt += __shfl_xor_sync(0xffffffffu, cnt, off);

    if ((tid & 31) == 0) wsum[tid >> 5] = cnt;
    __syncthreads();

    if (tid == 0) {
        int c = 0;
        #pragma unroll
        for (int w = 0; w < NWARPS; ++w)
            c += wsum[w];
        const float p = mem[row] + (float)c + noise[row];
        out[row] = (p >= thr[row]) ? 1.0f : 0.0f;
    }
}

extern "C" void kernel_launch(void* const* d_in, const int* in_sizes, int n_in,
                              void* d_out, int out_size) {
    const float* x      = (const float*)d_in[0];  // spike_input [1, 8192]
    const float* states = (const float*)d_in[1];  // synapse_states [8192, 8192]
    const float* mem    = (const float*)d_in[2];  // membrane_potential [8192]
    const float* thr    = (const float*)d_in[3];  // adaptive_threshold [8192]
    const float* noise  = (const float*)d_in[4];  // noise [8192]
    float* out = (float*)d_out;                   // spikes [8192]

    // Kernel 1: pack x (1 CTA), triggers PDL completion early.
    pack_x_kernel<<<1, NTHR>>>(x);

    // Kernel 2: main stream, launched with programmatic stream serialization
    // so its prologue (states loads) overlaps the pack kernel.
    cudaLaunchConfig_t cfg = {};
    cfg.gridDim  = dim3(OUT_F, 1, 1);
    cfg.blockDim = dim3(NTHR, 1, 1);
    cfg.dynamicSmemBytes = 0;
    cfg.stream = 0;  // legacy default stream (captured by harness)

    cudaLaunchAttribute attrs[1];
    attrs[0].id = cudaLaunchAttributeProgrammaticStreamSerialization;
    attrs[0].val.programmaticStreamSerializationAllowed = 1;
    cfg.attrs = attrs;
    cfg.numAttrs = 1;

    cudaLaunchKernelEx(&cfg, snn_bits_kernel, states, mem, thr, noise, out);
}